// round 10
// baseline (speedup 1.0000x reference)
#include <cuda_runtime.h>
#include <cstdint>

// ---------------------------------------------------------------------------
// PoincareEmbeddings: out[b,l,:] = custom ? T[cm] : Rw[rm] + lin_b
// where T[k] = lin_w @ mobius_add(logmap0(fixed[k]), train[k]) + lin_b
//
// R10 = R8 (GEMM reverted to the proven 314-CTA / 256-thread config) with
// k_mobius rebuilt single-stage: whole 64x320 block staged once in 83KB
// dynamic smem (stride 324 -> conflict-free permuted reads), ONE barrier,
// then bulk permuted emission. (R8's 20-barrier chunked version cost ~26us.)
// ---------------------------------------------------------------------------

constexpr int P_    = 300;
constexpr int PPAD  = 320;
constexpr int E_    = 256;
constexpr int Kc    = 20000;
constexpr int KP1   = Kc + 1;
constexpr int KROWS = 20096;      // 314 * 64
constexpr int NBT   = KROWS / 64; // 314 row-tiles
constexpr int VMAX  = 100000;

// A-permuted layout (per 64-row tile t, per BK=32 chunk it):
//   g_Mp[((t*10 + it)*16 + tile)*128 + lane*4 + reg]
//   tile = kk(0..3)*4 + m16(0..3); m16n8k8 A-fragment per lane (validated R7/R8).
__device__ float g_Mp[(size_t)KROWS * PPAD];
__device__ float g_T[(size_t)KROWS * E_];     // projected custom embeddings (+bias)
__device__ float g_Wp[(size_t)E_ * PPAD];     // lin_w, tf32, fragment-permuted
__device__ unsigned long long g_ptr[VMAX];    // per-vocab row pointer | custom flag

__device__ __forceinline__ float tf32_rna(float x) {
    float r;
    asm("cvt.rna.tf32.f32 %0, %1;" : "=f"(r) : "f"(x));
    return r;
}

// ---------------------------------------------------------------------------
// Prep A: lin_w -> g_Wp fragment-permuted tf32 (validated R7/R8).
// ---------------------------------------------------------------------------
__global__ void __launch_bounds__(256) k_wprep(const float* __restrict__ W) {
    int idx = blockIdx.x * 256 + threadIdx.x;
    if (idx >= E_ * PPAD) return;
    int slot = idx & 1;
    int lane = (idx >> 1) & 31;
    int t_n  = (idx >> 6) & 31;
    int t_k  = idx >> 11;
    int n = t_n * 8 + (lane >> 2);
    int k = t_k * 8 + (lane & 3) + slot * 4;
    g_Wp[idx] = (k < P_) ? tf32_rna(__ldg(W + (size_t)n * P_ + k)) : 0.f;
}

// ---------------------------------------------------------------------------
// Prep B: per-vocab fused row pointer (bit0 => custom row)
// ---------------------------------------------------------------------------
__global__ void __launch_bounds__(256) k_ptab(const int* __restrict__ v2c,
                                              const int* __restrict__ v2r,
                                              const float* __restrict__ Rw, int V) {
    int v = blockIdx.x * 256 + threadIdx.x;
    if (v >= V) return;
    int cm = __ldg(v2c + v);
    int rm = __ldg(v2r + v);
    unsigned long long p;
    if (cm) p = (unsigned long long)(g_T + (size_t)cm * E_) | 1ULL;
    else    p = (unsigned long long)(Rw  + (size_t)rm * E_);
    g_ptr[v] = p;
}

// ---------------------------------------------------------------------------
// Kernel 1: mobius -> fragment-permuted A, single-stage.
// 256 threads, 64 rows/block. Phase A: per-row (alpha,beta).
// Phase B: stage ALL 320 cols (stride 324: (r*324+k)%32 = (r*4+k)%32 ->
// lanes g=0..7,tg=0..3 of a fragment hit 32 distinct banks). ONE barrier.
// Phase C: emit 5120 permuted float4, 20 per thread, coalesced STG.128.
// ---------------------------------------------------------------------------
constexpr int MST   = 324;                 // stage row stride (floats)
constexpr int MOB_SMEMF = 64 * MST + 128;  // + coef[64][2]

__global__ void __launch_bounds__(256) k_mobius(const float* __restrict__ fixed_w,
                                                const float* __restrict__ train_w) {
    extern __shared__ float smem[];
    float* stage = smem;                 // [64][MST]
    float* coef  = smem + 64 * MST;      // [64][2]

    int tid = threadIdx.x;
    int bt  = blockIdx.x;
    int row = tid >> 2;                  // 0..63
    int sub = tid & 3;
    int gr  = bt * 64 + row;
    int rs  = (gr < KP1) ? gr : 0;
    const float* frow = fixed_w + (size_t)rs * P_;
    const float* trow = train_w + (size_t)rs * P_;

    // ---- Phase A: per-row coefficients (4 threads per row) ----
    {
        float sf2 = 0.f, sft = 0.f, st2 = 0.f;
        for (int p = sub * 4; p < P_; p += 16) {
            float4 fv = __ldg((const float4*)(frow + p));
            float4 tv = __ldg((const float4*)(trow + p));
            sf2 += fv.x*fv.x + fv.y*fv.y + fv.z*fv.z + fv.w*fv.w;
            sft += fv.x*tv.x + fv.y*tv.y + fv.z*tv.z + fv.w*tv.w;
            st2 += tv.x*tv.x + tv.y*tv.y + tv.z*tv.z + tv.w*tv.w;
        }
#pragma unroll
        for (int off = 1; off <= 2; off <<= 1) {
            sf2 += __shfl_xor_sync(0xFFFFFFFFu, sf2, off);
            sft += __shfl_xor_sync(0xFFFFFFFFu, sft, off);
            st2 += __shfl_xor_sync(0xFFFFFFFFu, st2, off);
        }
        if (sub == 0) {
            float norm  = sqrtf(sf2);
            float scale = (norm > 0.f) ? (atanhf(norm) / norm) : 1.0f;
            float x2 = scale * scale * sf2;
            float xy = scale * sft;
            float y2 = st2;
            float cu = 1.f + 2.f * xy + y2;
            float ct = 1.f - x2;
            float inv = 1.f / fmaxf(1.f + 2.f * xy + x2 * y2, 1e-15f);
            float alpha = cu * scale * inv;
            float beta  = ct * inv;
            if (gr >= KP1) { alpha = 0.f; beta = 0.f; }
            coef[row * 2]     = alpha;
            coef[row * 2 + 1] = beta;
        }
    }
    __syncthreads();

    // ---- Phase B: stage the full 64x320 block (each thread: 80 cols) ----
    {
        float alpha = coef[row * 2];
        float beta  = coef[row * 2 + 1];
        float* srow = stage + row * MST;
#pragma unroll
        for (int c = 0; c < 10; c++) {          // cols sub*4 + c*16 .. +3 (x4)
            int p0 = sub * 4 + c * 16;          // 4-thread interleave, f4-aligned
            float4 fv = make_float4(0.f,0.f,0.f,0.f), tv = fv;
            if (p0 < P_) { fv = __ldg((const float4*)(frow + p0));
                           tv = __ldg((const float4*)(trow + p0)); }
            srow[p0 + 0] = tf32_rna(alpha * fv.x + beta * tv.x);
            srow[p0 + 1] = tf32_rna(alpha * fv.y + beta * tv.y);
            srow[p0 + 2] = tf32_rna(alpha * fv.z + beta * tv.z);
            srow[p0 + 3] = tf32_rna(alpha * fv.w + beta * tv.w);
        }
        // cols 160..319 second half: p0 covers 0..156 above (sub*4+144 max=156).
        // extend: same pattern shifted by 160
#pragma unroll
        for (int c = 0; c < 10; c++) {
            int p0 = 160 + sub * 4 + c * 16;
            float4 fv = make_float4(0.f,0.f,0.f,0.f), tv = fv;
            if (p0 + 3 < P_)      { fv = __ldg((const float4*)(frow + p0));
                                    tv = __ldg((const float4*)(trow + p0)); }
            else if (p0 < P_) {     // straddle 300 (p0=296..299 can't happen: p0%4==0)
                fv = __ldg((const float4*)(frow + p0));
                tv = __ldg((const float4*)(trow + p0));
            }
            srow[p0 + 0] = (p0 + 0 < P_) ? tf32_rna(alpha * fv.x + beta * tv.x) : 0.f;
            srow[p0 + 1] = (p0 + 1 < P_) ? tf32_rna(alpha * fv.y + beta * tv.y) : 0.f;
            srow[p0 + 2] = (p0 + 2 < P_) ? tf32_rna(alpha * fv.z + beta * tv.z) : 0.f;
            srow[p0 + 3] = (p0 + 3 < P_) ? tf32_rna(alpha * fv.w + beta * tv.w) : 0.f;
        }
    }
    __syncthreads();

    // ---- Phase C: emit permuted fragments, 20 float4 per thread ----
    float4* dst = (float4*)(g_Mp + (size_t)bt * PPAD * 64);
#pragma unroll
    for (int h = 0; h < 20; h++) {
        int q    = tid + h * 256;       // 0..5119
        int it   = q >> 9;              // BK-chunk 0..9
        int q9   = q & 511;
        int tile = q9 >> 5;             // kk*4 + m16
        int lane = q9 & 31;
        int kk   = tile >> 2;
        int tm   = tile & 3;
        int g    = lane >> 2;
        int tg   = lane & 3;
        int r0 = tm * 16 + g;
        int k0 = it * 32 + kk * 8 + tg;
        dst[q] = make_float4(stage[r0 * MST + k0],       stage[(r0 + 8) * MST + k0],
                             stage[r0 * MST + k0 + 4],   stage[(r0 + 8) * MST + k0 + 4]);
    }
}

// ---------------------------------------------------------------------------
// Kernel 2: tf32 MMA GEMM (EXACT R8 config: BM=64 x BN=256, BK=32, 256 thr,
// 8 warps 2x4, warp 32x64, 2-stage cp.async, grid=314 -> clean wave balance).
// ---------------------------------------------------------------------------
constexpr int BK    = 32;
constexpr int NIT   = PPAD / BK;      // 10
constexpr int A_ST  = 2048;
constexpr int B_ST  = 8192;
constexpr int SMEMF = 2 * (A_ST + B_ST);

__device__ __forceinline__ void cpa16(uint32_t dst, const float* src) {
    asm volatile("cp.async.cg.shared.global [%0], [%1], 16;" :: "r"(dst), "l"(src));
}

__global__ void __launch_bounds__(256) k_gemm(const float* __restrict__ bias) {
    extern __shared__ float sm[];
    float* Bsm[2] = { sm,            sm + B_ST };
    float* Asm[2] = { sm + 2 * B_ST, sm + 2 * B_ST + A_ST };

    int tid  = threadIdx.x;
    int warp = tid >> 5;
    int lane = tid & 31;
    int wm = warp >> 2;
    int wn = warp & 3;
    int g  = lane >> 2;
    int tg = lane & 3;
    int bt = blockIdx.x;
    int rowBase = bt * 64;

    auto load_stage = [&](int s, int it) {
        const float* Bsrc = g_Wp + (size_t)it * B_ST;
#pragma unroll
        for (int j = 0; j < 8; j++) {
            int c = (tid + j * 256) * 4;
            cpa16((uint32_t)__cvta_generic_to_shared(Bsm[s] + c), Bsrc + c);
        }
        const float* Asrc = g_Mp + ((size_t)bt * NIT + it) * A_ST;
#pragma unroll
        for (int j = 0; j < 2; j++) {
            int c = (tid + j * 256) * 4;
            cpa16((uint32_t)__cvta_generic_to_shared(Asm[s] + c), Asrc + c);
        }
    };

    float acc[2][8][4];
#pragma unroll
    for (int mi = 0; mi < 2; mi++)
#pragma unroll
        for (int ni = 0; ni < 8; ni++)
#pragma unroll
            for (int r = 0; r < 4; r++) acc[mi][ni][r] = 0.f;

    load_stage(0, 0);
    asm volatile("cp.async.commit_group;");

    for (int it = 0; it < NIT; it++) {
        int cur = it & 1;
        if (it + 1 < NIT) load_stage(cur ^ 1, it + 1);
        asm volatile("cp.async.commit_group;");
        asm volatile("cp.async.wait_group 1;");
        __syncthreads();

        const float* Ac = Asm[cur];
        const float* Bc = Bsm[cur];
#pragma unroll
        for (int kk = 0; kk < 4; kk++) {
            uint32_t a[2][4];
#pragma unroll
            for (int mi = 0; mi < 2; mi++) {
                float4 av = *(const float4*)(Ac + ((kk * 4 + wm * 2 + mi) * 32 + lane) * 4);
                a[mi][0] = __float_as_uint(av.x);
                a[mi][1] = __float_as_uint(av.y);
                a[mi][2] = __float_as_uint(av.z);
                a[mi][3] = __float_as_uint(av.w);
            }
#pragma unroll
            for (int ni = 0; ni < 8; ni++) {
                float2 bv = *(const float2*)(Bc + ((kk * 32 + wn * 8 + ni) * 32 + lane) * 2);
                uint32_t b0 = __float_as_uint(bv.x);
                uint32_t b1 = __float_as_uint(bv.y);
#pragma unroll
                for (int mi = 0; mi < 2; mi++) {
                    asm volatile(
                        "mma.sync.aligned.m16n8k8.row.col.f32.tf32.tf32.f32 "
                        "{%0,%1,%2,%3}, {%4,%5,%6,%7}, {%8,%9}, {%0,%1,%2,%3};"
                        : "+f"(acc[mi][ni][0]), "+f"(acc[mi][ni][1]),
                          "+f"(acc[mi][ni][2]), "+f"(acc[mi][ni][3])
                        : "r"(a[mi][0]), "r"(a[mi][1]), "r"(a[mi][2]), "r"(a[mi][3]),
                          "r"(b0), "r"(b1));
                }
            }
        }
        __syncthreads();
    }

#pragma unroll
    for (int mi = 0; mi < 2; mi++) {
#pragma unroll
        for (int ni = 0; ni < 8; ni++) {
            int col = wn * 64 + ni * 8 + tg * 2;
            float bx = __ldg(bias + col), by = __ldg(bias + col + 1);
            int r0 = rowBase + wm * 32 + mi * 16 + g;
            *(float2*)(g_T + (size_t)r0 * E_ + col) =
                make_float2(acc[mi][ni][0] + bx, acc[mi][ni][1] + by);
            *(float2*)(g_T + (size_t)(r0 + 8) * E_ + col) =
                make_float2(acc[mi][ni][2] + bx, acc[mi][ni][3] + by);
        }
    }
}

// ---------------------------------------------------------------------------
// Kernel 3: gather (proven, at its traffic roofline).
// ---------------------------------------------------------------------------
__global__ void __launch_bounds__(256) k_gather(const int* __restrict__ x,
                                                const float* __restrict__ lin_b,
                                                float4* __restrict__ out,
                                                int ntok) {
    int gtid = blockIdx.x * 256 + threadIdx.x;
    int tok = gtid >> 5;
    int e4  = gtid & 31;
    if (tok >= ntok) return;

    int v = __ldg(x + tok);
    unsigned long long t = __ldg(g_ptr + v);
    float s = (t & 1ULL) ? 0.f : 1.f;
    const float4* src = (const float4*)(t & ~1ULL);

    float4 a0 = __ldg(src + e4);
    float4 a1 = __ldg(src + e4 + 32);
    float4 b0 = __ldg((const float4*)lin_b + e4);
    float4 b1 = __ldg((const float4*)lin_b + e4 + 32);

    float4* dst = out + (size_t)tok * 64;
    __stcs(dst + e4,      make_float4(a0.x + s * b0.x, a0.y + s * b0.y,
                                      a0.z + s * b0.z, a0.w + s * b0.w));
    __stcs(dst + e4 + 32, make_float4(a1.x + s * b1.x, a1.y + s * b1.y,
                                      a1.z + s * b1.z, a1.w + s * b1.w));
}

// ---------------------------------------------------------------------------
// Launch. Inputs: 0:x 1:custom_indices(unused) 2:v2c 3:v2r
//  4:custom_fixed_w 5:custom_train_w 6:regular_w 7:lin_w 8:lin_b
// ---------------------------------------------------------------------------
extern "C" void kernel_launch(void* const* d_in, const int* in_sizes, int n_in,
                              void* d_out, int out_size) {
    const int*   x    = (const int*)d_in[0];
    const int*   v2c  = (const int*)d_in[2];
    const int*   v2r  = (const int*)d_in[3];
    const float* fw   = (const float*)d_in[4];
    const float* tw   = (const float*)d_in[5];
    const float* Rw   = (const float*)d_in[6];
    const float* W    = (const float*)d_in[7];
    const float* bias = (const float*)d_in[8];
    float4* out = (float4*)d_out;

    int ntok = in_sizes[0];
    int V    = in_sizes[2];

    static bool init_done = false;
    if (!init_done) {
        cudaFuncSetAttribute(k_gemm, cudaFuncAttributeMaxDynamicSharedMemorySize,
                             SMEMF * (int)sizeof(float));
        cudaFuncSetAttribute(k_mobius, cudaFuncAttributeMaxDynamicSharedMemorySize,
                             MOB_SMEMF * (int)sizeof(float));
        init_done = true;
    }

    k_wprep<<<(E_ * PPAD + 255) / 256, 256>>>(W);
    k_ptab<<<(V + 255) / 256, 256>>>(v2c, v2r, Rw, V);
    k_mobius<<<NBT, 256, MOB_SMEMF * sizeof(float)>>>(fw, tw);
    k_gemm<<<NBT, 256, SMEMF * sizeof(float)>>>(bias);

    int gthreads = ntok * 32;
    k_gather<<<(gthreads + 255) / 256, 256>>>(x, bias, out, ntok);
}

// round 11
// speedup vs baseline: 1.0983x; 1.0983x over previous
#include <cuda_runtime.h>
#include <cstdint>

// ---------------------------------------------------------------------------
// PoincareEmbeddings: out[b,l,:] = custom ? T[cm] : Rw[rm] + lin_b
// where T[k] = lin_w @ mobius_add(logmap0(fixed[k]), train[k]) + lin_b
//
// R11 = R8 GEMM (proven 33us) + gather (proven 69us, roofline) + NEW mobius:
// one-warp-per-row register-resident compute (inputs read ONCE, like R4's
// 14us version) feeding R10's validated permuted emission via one smem stage
// and a single barrier.
// ---------------------------------------------------------------------------

constexpr int P_    = 300;
constexpr int PPAD  = 320;
constexpr int E_    = 256;
constexpr int Kc    = 20000;
constexpr int KP1   = Kc + 1;
constexpr int KROWS = 20096;      // 314 * 64
constexpr int NBT   = KROWS / 64; // 314 row-tiles
constexpr int VMAX  = 100000;

// A-permuted layout (per 64-row tile t, per BK=32 chunk it):
//   g_Mp[((t*10 + it)*16 + tile)*128 + lane*4 + reg]
//   tile = kk(0..3)*4 + m16(0..3); m16n8k8 A-fragment per lane (validated R7-R10).
__device__ float g_Mp[(size_t)KROWS * PPAD];
__device__ float g_T[(size_t)KROWS * E_];     // projected custom embeddings (+bias)
__device__ float g_Wp[(size_t)E_ * PPAD];     // lin_w, tf32, fragment-permuted
__device__ unsigned long long g_ptr[VMAX];    // per-vocab row pointer | custom flag

__device__ __forceinline__ float tf32_rna(float x) {
    float r;
    asm("cvt.rna.tf32.f32 %0, %1;" : "=f"(r) : "f"(x));
    return r;
}

// ---------------------------------------------------------------------------
// Prep A: lin_w -> g_Wp fragment-permuted tf32 (validated R7-R10).
// ---------------------------------------------------------------------------
__global__ void __launch_bounds__(256) k_wprep(const float* __restrict__ W) {
    int idx = blockIdx.x * 256 + threadIdx.x;
    if (idx >= E_ * PPAD) return;
    int slot = idx & 1;
    int lane = (idx >> 1) & 31;
    int t_n  = (idx >> 6) & 31;
    int t_k  = idx >> 11;
    int n = t_n * 8 + (lane >> 2);
    int k = t_k * 8 + (lane & 3) + slot * 4;
    g_Wp[idx] = (k < P_) ? tf32_rna(__ldg(W + (size_t)n * P_ + k)) : 0.f;
}

// ---------------------------------------------------------------------------
// Prep B: per-vocab fused row pointer (bit0 => custom row)
// ---------------------------------------------------------------------------
__global__ void __launch_bounds__(256) k_ptab(const int* __restrict__ v2c,
                                              const int* __restrict__ v2r,
                                              const float* __restrict__ Rw, int V) {
    int v = blockIdx.x * 256 + threadIdx.x;
    if (v >= V) return;
    int cm = __ldg(v2c + v);
    int rm = __ldg(v2r + v);
    unsigned long long p;
    if (cm) p = (unsigned long long)(g_T + (size_t)cm * E_) | 1ULL;
    else    p = (unsigned long long)(Rw  + (size_t)rm * E_);
    g_ptr[v] = p;
}

// ---------------------------------------------------------------------------
// Kernel 1: mobius -> fragment-permuted A.
// 256 threads = 8 warps; each warp handles 8 rows sequentially (64 rows/CTA).
// Per row: 10 f + 10 t values per lane in REGISTERS (input read once),
// full-warp butterfly reduction for the three dot products, all lanes get
// alpha/beta, coalesced STS into stage[64][324] (stride 324 -> conflict-free
// permuted reads). One barrier, then R10's validated permuted emission.
// ---------------------------------------------------------------------------
constexpr int MST       = 324;             // stage row stride (floats)
constexpr int MOB_SMEMF = 64 * MST;        // 82944 bytes

__global__ void __launch_bounds__(256) k_mobius(const float* __restrict__ fixed_w,
                                                const float* __restrict__ train_w) {
    extern __shared__ float stage[];       // [64][MST]

    int tid  = threadIdx.x;
    int warp = tid >> 5;
    int lane = tid & 31;
    int bt   = blockIdx.x;

    for (int r8 = 0; r8 < 8; r8++) {
        int row = warp * 8 + r8;           // 0..63
        int gr  = bt * 64 + row;
        int rs  = (gr < KP1) ? gr : 0;
        const float* f = fixed_w + (size_t)rs * P_;
        const float* t = train_w + (size_t)rs * P_;

        float fr[10], tr[10];
        float sf2 = 0.f, sft = 0.f, st2 = 0.f;
#pragma unroll
        for (int i = 0; i < 10; i++) {
            int p = lane + i * 32;
            float fv = (p < P_) ? __ldg(f + p) : 0.f;
            float tv = (p < P_) ? __ldg(t + p) : 0.f;
            fr[i] = fv; tr[i] = tv;
            sf2 += fv * fv;
            sft += fv * tv;
            st2 += tv * tv;
        }
#pragma unroll
        for (int off = 16; off; off >>= 1) {
            sf2 += __shfl_xor_sync(0xFFFFFFFFu, sf2, off);
            sft += __shfl_xor_sync(0xFFFFFFFFu, sft, off);
            st2 += __shfl_xor_sync(0xFFFFFFFFu, st2, off);
        }

        float norm  = sqrtf(sf2);
        float scale = (norm > 0.f) ? (atanhf(norm) / norm) : 1.0f;
        float x2 = scale * scale * sf2;
        float xy = scale * sft;
        float y2 = st2;
        float cu = 1.f + 2.f * xy + y2;
        float ct = 1.f - x2;
        float inv = 1.f / fmaxf(1.f + 2.f * xy + x2 * y2, 1e-15f);
        float alpha = cu * scale * inv;
        float beta  = ct * inv;
        if (gr >= KP1) { alpha = 0.f; beta = 0.f; }   // GEMM padding rows -> 0

        float* srow = stage + row * MST;
#pragma unroll
        for (int i = 0; i < 10; i++) {
            int p = lane + i * 32;                    // covers 0..319 exactly
            srow[p] = tf32_rna(alpha * fr[i] + beta * tr[i]);
        }
    }
    __syncthreads();

    // ---- permuted emission (byte-identical to R10 phase C; validated) ----
    float4* dst = (float4*)(g_Mp + (size_t)bt * PPAD * 64);
#pragma unroll
    for (int h = 0; h < 20; h++) {
        int q    = tid + h * 256;       // 0..5119
        int it   = q >> 9;              // BK-chunk 0..9
        int q9   = q & 511;
        int tile = q9 >> 5;             // kk*4 + m16
        int ln   = q9 & 31;
        int kk   = tile >> 2;
        int tm   = tile & 3;
        int g    = ln >> 2;
        int tg   = ln & 3;
        int r0 = tm * 16 + g;
        int k0 = it * 32 + kk * 8 + tg;
        dst[q] = make_float4(stage[r0 * MST + k0],     stage[(r0 + 8) * MST + k0],
                             stage[r0 * MST + k0 + 4], stage[(r0 + 8) * MST + k0 + 4]);
    }
}

// ---------------------------------------------------------------------------
// Kernel 2: tf32 MMA GEMM (EXACT R8 config: BM=64 x BN=256, BK=32, 256 thr,
// 8 warps 2x4, warp 32x64, 2-stage cp.async, grid=314 -> clean wave balance).
// Measured 33us twice; do not touch.
// ---------------------------------------------------------------------------
constexpr int BK    = 32;
constexpr int NIT   = PPAD / BK;      // 10
constexpr int A_ST  = 2048;
constexpr int B_ST  = 8192;
constexpr int SMEMF = 2 * (A_ST + B_ST);

__device__ __forceinline__ void cpa16(uint32_t dst, const float* src) {
    asm volatile("cp.async.cg.shared.global [%0], [%1], 16;" :: "r"(dst), "l"(src));
}

__global__ void __launch_bounds__(256) k_gemm(const float* __restrict__ bias) {
    extern __shared__ float sm[];
    float* Bsm[2] = { sm,            sm + B_ST };
    float* Asm[2] = { sm + 2 * B_ST, sm + 2 * B_ST + A_ST };

    int tid  = threadIdx.x;
    int warp = tid >> 5;
    int lane = tid & 31;
    int wm = warp >> 2;
    int wn = warp & 3;
    int g  = lane >> 2;
    int tg = lane & 3;
    int bt = blockIdx.x;
    int rowBase = bt * 64;

    auto load_stage = [&](int s, int it) {
        const float* Bsrc = g_Wp + (size_t)it * B_ST;
#pragma unroll
        for (int j = 0; j < 8; j++) {
            int c = (tid + j * 256) * 4;
            cpa16((uint32_t)__cvta_generic_to_shared(Bsm[s] + c), Bsrc + c);
        }
        const float* Asrc = g_Mp + ((size_t)bt * NIT + it) * A_ST;
#pragma unroll
        for (int j = 0; j < 2; j++) {
            int c = (tid + j * 256) * 4;
            cpa16((uint32_t)__cvta_generic_to_shared(Asm[s] + c), Asrc + c);
        }
    };

    float acc[2][8][4];
#pragma unroll
    for (int mi = 0; mi < 2; mi++)
#pragma unroll
        for (int ni = 0; ni < 8; ni++)
#pragma unroll
            for (int r = 0; r < 4; r++) acc[mi][ni][r] = 0.f;

    load_stage(0, 0);
    asm volatile("cp.async.commit_group;");

    for (int it = 0; it < NIT; it++) {
        int cur = it & 1;
        if (it + 1 < NIT) load_stage(cur ^ 1, it + 1);
        asm volatile("cp.async.commit_group;");
        asm volatile("cp.async.wait_group 1;");
        __syncthreads();

        const float* Ac = Asm[cur];
        const float* Bc = Bsm[cur];
#pragma unroll
        for (int kk = 0; kk < 4; kk++) {
            uint32_t a[2][4];
#pragma unroll
            for (int mi = 0; mi < 2; mi++) {
                float4 av = *(const float4*)(Ac + ((kk * 4 + wm * 2 + mi) * 32 + lane) * 4);
                a[mi][0] = __float_as_uint(av.x);
                a[mi][1] = __float_as_uint(av.y);
                a[mi][2] = __float_as_uint(av.z);
                a[mi][3] = __float_as_uint(av.w);
            }
#pragma unroll
            for (int ni = 0; ni < 8; ni++) {
                float2 bv = *(const float2*)(Bc + ((kk * 32 + wn * 8 + ni) * 32 + lane) * 2);
                uint32_t b0 = __float_as_uint(bv.x);
                uint32_t b1 = __float_as_uint(bv.y);
#pragma unroll
                for (int mi = 0; mi < 2; mi++) {
                    asm volatile(
                        "mma.sync.aligned.m16n8k8.row.col.f32.tf32.tf32.f32 "
                        "{%0,%1,%2,%3}, {%4,%5,%6,%7}, {%8,%9}, {%0,%1,%2,%3};"
                        : "+f"(acc[mi][ni][0]), "+f"(acc[mi][ni][1]),
                          "+f"(acc[mi][ni][2]), "+f"(acc[mi][ni][3])
                        : "r"(a[mi][0]), "r"(a[mi][1]), "r"(a[mi][2]), "r"(a[mi][3]),
                          "r"(b0), "r"(b1));
                }
            }
        }
        __syncthreads();
    }

#pragma unroll
    for (int mi = 0; mi < 2; mi++) {
#pragma unroll
        for (int ni = 0; ni < 8; ni++) {
            int col = wn * 64 + ni * 8 + tg * 2;
            float bx = __ldg(bias + col), by = __ldg(bias + col + 1);
            int r0 = rowBase + wm * 32 + mi * 16 + g;
            *(float2*)(g_T + (size_t)r0 * E_ + col) =
                make_float2(acc[mi][ni][0] + bx, acc[mi][ni][1] + by);
            *(float2*)(g_T + (size_t)(r0 + 8) * E_ + col) =
                make_float2(acc[mi][ni][2] + bx, acc[mi][ni][3] + by);
        }
    }
}

// ---------------------------------------------------------------------------
// Kernel 3: gather (proven, at its traffic roofline).
// ---------------------------------------------------------------------------
__global__ void __launch_bounds__(256) k_gather(const int* __restrict__ x,
                                                const float* __restrict__ lin_b,
                                                float4* __restrict__ out,
                                                int ntok) {
    int gtid = blockIdx.x * 256 + threadIdx.x;
    int tok = gtid >> 5;
    int e4  = gtid & 31;
    if (tok >= ntok) return;

    int v = __ldg(x + tok);
    unsigned long long t = __ldg(g_ptr + v);
    float s = (t & 1ULL) ? 0.f : 1.f;
    const float4* src = (const float4*)(t & ~1ULL);

    float4 a0 = __ldg(src + e4);
    float4 a1 = __ldg(src + e4 + 32);
    float4 b0 = __ldg((const float4*)lin_b + e4);
    float4 b1 = __ldg((const float4*)lin_b + e4 + 32);

    float4* dst = out + (size_t)tok * 64;
    __stcs(dst + e4,      make_float4(a0.x + s * b0.x, a0.y + s * b0.y,
                                      a0.z + s * b0.z, a0.w + s * b0.w));
    __stcs(dst + e4 + 32, make_float4(a1.x + s * b1.x, a1.y + s * b1.y,
                                      a1.z + s * b1.z, a1.w + s * b1.w));
}

// ---------------------------------------------------------------------------
// Launch. Inputs: 0:x 1:custom_indices(unused) 2:v2c 3:v2r
//  4:custom_fixed_w 5:custom_train_w 6:regular_w 7:lin_w 8:lin_b
// ---------------------------------------------------------------------------
extern "C" void kernel_launch(void* const* d_in, const int* in_sizes, int n_in,
                              void* d_out, int out_size) {
    const int*   x    = (const int*)d_in[0];
    const int*   v2c  = (const int*)d_in[2];
    const int*   v2r  = (const int*)d_in[3];
    const float* fw   = (const float*)d_in[4];
    const float* tw   = (const float*)d_in[5];
    const float* Rw   = (const float*)d_in[6];
    const float* W    = (const float*)d_in[7];
    const float* bias = (const float*)d_in[8];
    float4* out = (float4*)d_out;

    int ntok = in_sizes[0];
    int V    = in_sizes[2];

    static bool init_done = false;
    if (!init_done) {
        cudaFuncSetAttribute(k_gemm, cudaFuncAttributeMaxDynamicSharedMemorySize,
                             SMEMF * (int)sizeof(float));
        cudaFuncSetAttribute(k_mobius, cudaFuncAttributeMaxDynamicSharedMemorySize,
                             MOB_SMEMF * (int)sizeof(float));
        init_done = true;
    }

    k_wprep<<<(E_ * PPAD + 255) / 256, 256>>>(W);
    k_ptab<<<(V + 255) / 256, 256>>>(v2c, v2r, Rw, V);
    k_mobius<<<NBT, 256, MOB_SMEMF * sizeof(float)>>>(fw, tw);
    k_gemm<<<NBT, 256, SMEMF * sizeof(float)>>>(bias);

    int gthreads = ntok * 32;
    k_gather<<<(gthreads + 255) / 256, 256>>>(x, bias, out, ntok);
}

// round 12
// speedup vs baseline: 1.1848x; 1.0787x over previous
#include <cuda_runtime.h>
#include <cstdint>

// ---------------------------------------------------------------------------
// PoincareEmbeddings: out[b,l,:] = custom ? T[cm] : Rw[rm] + lin_b
// where T[k] = lin_w @ mobius_add(logmap0(fixed[k]), train[k]) + lin_b
//
// R12 = R11 with k_mobius re-grained: 16 rows per CTA (the emission-closed
// group of the permuted layout: tile tm only touches rows tm*16+g, tm*16+8+g).
// Stage drops 83KB -> 20.7KB static smem => ~8 CTAs/SM and grid 1256 for the
// latency-bound load/reduce phase. g_Mp bytes identical to R11 (validated).
// ---------------------------------------------------------------------------

constexpr int P_    = 300;
constexpr int PPAD  = 320;
constexpr int E_    = 256;
constexpr int Kc    = 20000;
constexpr int KP1   = Kc + 1;
constexpr int KROWS = 20096;      // 314 * 64 == 1256 * 16
constexpr int NBT   = KROWS / 64; // 314 GEMM row-tiles
constexpr int NMB   = KROWS / 16; // 1256 mobius blocks
constexpr int VMAX  = 100000;

// A-permuted layout (per 64-row tile t, per BK=32 chunk it):
//   g_Mp[((t*10 + it)*16 + kk*4 + tm)*128 + lane*4 + reg]
//   m16n8k8 A-fragment per lane (validated R7-R11).
__device__ float g_Mp[(size_t)KROWS * PPAD];
__device__ float g_T[(size_t)KROWS * E_];     // projected custom embeddings (+bias)
__device__ float g_Wp[(size_t)E_ * PPAD];     // lin_w, tf32, fragment-permuted
__device__ unsigned long long g_ptr[VMAX];    // per-vocab row pointer | custom flag

__device__ __forceinline__ float tf32_rna(float x) {
    float r;
    asm("cvt.rna.tf32.f32 %0, %1;" : "=f"(r) : "f"(x));
    return r;
}

// ---------------------------------------------------------------------------
// Prep A: lin_w -> g_Wp fragment-permuted tf32 (validated R7-R11).
// ---------------------------------------------------------------------------
__global__ void __launch_bounds__(256) k_wprep(const float* __restrict__ W) {
    int idx = blockIdx.x * 256 + threadIdx.x;
    if (idx >= E_ * PPAD) return;
    int slot = idx & 1;
    int lane = (idx >> 1) & 31;
    int t_n  = (idx >> 6) & 31;
    int t_k  = idx >> 11;
    int n = t_n * 8 + (lane >> 2);
    int k = t_k * 8 + (lane & 3) + slot * 4;
    g_Wp[idx] = (k < P_) ? tf32_rna(__ldg(W + (size_t)n * P_ + k)) : 0.f;
}

// ---------------------------------------------------------------------------
// Prep B: per-vocab fused row pointer (bit0 => custom row)
// ---------------------------------------------------------------------------
__global__ void __launch_bounds__(256) k_ptab(const int* __restrict__ v2c,
                                              const int* __restrict__ v2r,
                                              const float* __restrict__ Rw, int V) {
    int v = blockIdx.x * 256 + threadIdx.x;
    if (v >= V) return;
    int cm = __ldg(v2c + v);
    int rm = __ldg(v2r + v);
    unsigned long long p;
    if (cm) p = (unsigned long long)(g_T + (size_t)cm * E_) | 1ULL;
    else    p = (unsigned long long)(Rw  + (size_t)rm * E_);
    g_ptr[v] = p;
}

// ---------------------------------------------------------------------------
// Kernel 1: mobius -> fragment-permuted A. 16 rows/CTA, 256 threads = 8 warps,
// 2 rows per warp (register-resident, input read ONCE, full-warp butterfly).
// Stage [16][324] (20.7KB static): stride 324 -> conflict-free permuted reads.
// One barrier, then 1280 float4 emission (5/thread, coalesced STG.128).
// ---------------------------------------------------------------------------
constexpr int MST = 324;   // stage row stride (floats); 324 % 32 == 4

__global__ void __launch_bounds__(256) k_mobius(const float* __restrict__ fixed_w,
                                                const float* __restrict__ train_w) {
    __shared__ float stage[16 * MST];

    int tid  = threadIdx.x;
    int warp = tid >> 5;
    int lane = tid & 31;
    int mb   = blockIdx.x;               // 16-row block id
    int rowBase = mb * 16;

#pragma unroll
    for (int r2 = 0; r2 < 2; r2++) {
        int row = warp * 2 + r2;         // 0..15
        int gr  = rowBase + row;
        int rs  = (gr < KP1) ? gr : 0;
        const float* f = fixed_w + (size_t)rs * P_;
        const float* t = train_w + (size_t)rs * P_;

        float fr[10], tr[10];
        float sf2 = 0.f, sft = 0.f, st2 = 0.f;
#pragma unroll
        for (int i = 0; i < 10; i++) {
            int p = lane + i * 32;
            float fv = (p < P_) ? __ldg(f + p) : 0.f;
            float tv = (p < P_) ? __ldg(t + p) : 0.f;
            fr[i] = fv; tr[i] = tv;
            sf2 += fv * fv;
            sft += fv * tv;
            st2 += tv * tv;
        }
#pragma unroll
        for (int off = 16; off; off >>= 1) {
            sf2 += __shfl_xor_sync(0xFFFFFFFFu, sf2, off);
            sft += __shfl_xor_sync(0xFFFFFFFFu, sft, off);
            st2 += __shfl_xor_sync(0xFFFFFFFFu, st2, off);
        }

        float norm  = sqrtf(sf2);
        float scale = (norm > 0.f) ? (atanhf(norm) / norm) : 1.0f;
        float x2 = scale * scale * sf2;
        float xy = scale * sft;
        float y2 = st2;
        float cu = 1.f + 2.f * xy + y2;
        float ct = 1.f - x2;
        float inv = 1.f / fmaxf(1.f + 2.f * xy + x2 * y2, 1e-15f);
        float alpha = cu * scale * inv;
        float beta  = ct * inv;
        if (gr >= KP1) { alpha = 0.f; beta = 0.f; }   // GEMM padding rows -> 0

        float* srow = stage + row * MST;
#pragma unroll
        for (int i = 0; i < 10; i++) {
            int p = lane + i * 32;                    // covers 0..319 exactly
            srow[p] = tf32_rna(alpha * fr[i] + beta * tr[i]);
        }
    }
    __syncthreads();

    // ---- permuted emission: this CTA is GEMM tile t = mb/4, sub-tile tm = mb%4.
    // fragment (it, kk): dst index ((t*10+it)*16 + kk*4+tm)*32 + lane,
    // sourced from local rows g, g+8, cols it*32+kk*8+tg (+4).
    int t_  = mb >> 2;
    int tm  = mb & 3;
    float4* dstBase = (float4*)g_Mp;
#pragma unroll
    for (int h = 0; h < 5; h++) {
        int q   = tid + h * 256;        // 0..1279
        int it  = q >> 7;               // 0..9
        int rem = q & 127;
        int kk  = rem >> 5;             // 0..3
        int ln  = rem & 31;
        int g   = ln >> 2;
        int tg  = ln & 3;
        int k0  = it * 32 + kk * 8 + tg;
        size_t di = ((size_t)(t_ * 10 + it) * 16 + kk * 4 + tm) * 32 + ln;
        dstBase[di] = make_float4(stage[g * MST + k0],       stage[(g + 8) * MST + k0],
                                  stage[g * MST + k0 + 4],   stage[(g + 8) * MST + k0 + 4]);
    }
}

// ---------------------------------------------------------------------------
// Kernel 2: tf32 MMA GEMM (EXACT R8/R11 config, measured 33us three times:
// BM=64 x BN=256, BK=32, 256 thr, 8 warps 2x4, warp 32x64, 2-stage cp.async,
// grid=314). Do not touch.
// ---------------------------------------------------------------------------
constexpr int BK    = 32;
constexpr int NIT   = PPAD / BK;      // 10
constexpr int A_ST  = 2048;
constexpr int B_ST  = 8192;
constexpr int SMEMF = 2 * (A_ST + B_ST);

__device__ __forceinline__ void cpa16(uint32_t dst, const float* src) {
    asm volatile("cp.async.cg.shared.global [%0], [%1], 16;" :: "r"(dst), "l"(src));
}

__global__ void __launch_bounds__(256) k_gemm(const float* __restrict__ bias) {
    extern __shared__ float sm[];
    float* Bsm[2] = { sm,            sm + B_ST };
    float* Asm[2] = { sm + 2 * B_ST, sm + 2 * B_ST + A_ST };

    int tid  = threadIdx.x;
    int warp = tid >> 5;
    int lane = tid & 31;
    int wm = warp >> 2;
    int wn = warp & 3;
    int g  = lane >> 2;
    int tg = lane & 3;
    int bt = blockIdx.x;
    int rowBase = bt * 64;

    auto load_stage = [&](int s, int it) {
        const float* Bsrc = g_Wp + (size_t)it * B_ST;
#pragma unroll
        for (int j = 0; j < 8; j++) {
            int c = (tid + j * 256) * 4;
            cpa16((uint32_t)__cvta_generic_to_shared(Bsm[s] + c), Bsrc + c);
        }
        const float* Asrc = g_Mp + ((size_t)bt * NIT + it) * A_ST;
#pragma unroll
        for (int j = 0; j < 2; j++) {
            int c = (tid + j * 256) * 4;
            cpa16((uint32_t)__cvta_generic_to_shared(Asm[s] + c), Asrc + c);
        }
    };

    float acc[2][8][4];
#pragma unroll
    for (int mi = 0; mi < 2; mi++)
#pragma unroll
        for (int ni = 0; ni < 8; ni++)
#pragma unroll
            for (int r = 0; r < 4; r++) acc[mi][ni][r] = 0.f;

    load_stage(0, 0);
    asm volatile("cp.async.commit_group;");

    for (int it = 0; it < NIT; it++) {
        int cur = it & 1;
        if (it + 1 < NIT) load_stage(cur ^ 1, it + 1);
        asm volatile("cp.async.commit_group;");
        asm volatile("cp.async.wait_group 1;");
        __syncthreads();

        const float* Ac = Asm[cur];
        const float* Bc = Bsm[cur];
#pragma unroll
        for (int kk = 0; kk < 4; kk++) {
            uint32_t a[2][4];
#pragma unroll
            for (int mi = 0; mi < 2; mi++) {
                float4 av = *(const float4*)(Ac + ((kk * 4 + wm * 2 + mi) * 32 + lane) * 4);
                a[mi][0] = __float_as_uint(av.x);
                a[mi][1] = __float_as_uint(av.y);
                a[mi][2] = __float_as_uint(av.z);
                a[mi][3] = __float_as_uint(av.w);
            }
#pragma unroll
            for (int ni = 0; ni < 8; ni++) {
                float2 bv = *(const float2*)(Bc + ((kk * 32 + wn * 8 + ni) * 32 + lane) * 2);
                uint32_t b0 = __float_as_uint(bv.x);
                uint32_t b1 = __float_as_uint(bv.y);
#pragma unroll
                for (int mi = 0; mi < 2; mi++) {
                    asm volatile(
                        "mma.sync.aligned.m16n8k8.row.col.f32.tf32.tf32.f32 "
                        "{%0,%1,%2,%3}, {%4,%5,%6,%7}, {%8,%9}, {%0,%1,%2,%3};"
                        : "+f"(acc[mi][ni][0]), "+f"(acc[mi][ni][1]),
                          "+f"(acc[mi][ni][2]), "+f"(acc[mi][ni][3])
                        : "r"(a[mi][0]), "r"(a[mi][1]), "r"(a[mi][2]), "r"(a[mi][3]),
                          "r"(b0), "r"(b1));
                }
            }
        }
        __syncthreads();
    }

#pragma unroll
    for (int mi = 0; mi < 2; mi++) {
#pragma unroll
        for (int ni = 0; ni < 8; ni++) {
            int col = wn * 64 + ni * 8 + tg * 2;
            float bx = __ldg(bias + col), by = __ldg(bias + col + 1);
            int r0 = rowBase + wm * 32 + mi * 16 + g;
            *(float2*)(g_T + (size_t)r0 * E_ + col) =
                make_float2(acc[mi][ni][0] + bx, acc[mi][ni][1] + by);
            *(float2*)(g_T + (size_t)(r0 + 8) * E_ + col) =
                make_float2(acc[mi][ni][2] + bx, acc[mi][ni][3] + by);
        }
    }
}

// ---------------------------------------------------------------------------
// Kernel 3: gather (proven, at its traffic roofline).
// ---------------------------------------------------------------------------
__global__ void __launch_bounds__(256) k_gather(const int* __restrict__ x,
                                                const float* __restrict__ lin_b,
                                                float4* __restrict__ out,
                                                int ntok) {
    int gtid = blockIdx.x * 256 + threadIdx.x;
    int tok = gtid >> 5;
    int e4  = gtid & 31;
    if (tok >= ntok) return;

    int v = __ldg(x + tok);
    unsigned long long t = __ldg(g_ptr + v);
    float s = (t & 1ULL) ? 0.f : 1.f;
    const float4* src = (const float4*)(t & ~1ULL);

    float4 a0 = __ldg(src + e4);
    float4 a1 = __ldg(src + e4 + 32);
    float4 b0 = __ldg((const float4*)lin_b + e4);
    float4 b1 = __ldg((const float4*)lin_b + e4 + 32);

    float4* dst = out + (size_t)tok * 64;
    __stcs(dst + e4,      make_float4(a0.x + s * b0.x, a0.y + s * b0.y,
                                      a0.z + s * b0.z, a0.w + s * b0.w));
    __stcs(dst + e4 + 32, make_float4(a1.x + s * b1.x, a1.y + s * b1.y,
                                      a1.z + s * b1.z, a1.w + s * b1.w));
}

// ---------------------------------------------------------------------------
// Launch. Inputs: 0:x 1:custom_indices(unused) 2:v2c 3:v2r
//  4:custom_fixed_w 5:custom_train_w 6:regular_w 7:lin_w 8:lin_b
// ---------------------------------------------------------------------------
extern "C" void kernel_launch(void* const* d_in, const int* in_sizes, int n_in,
                              void* d_out, int out_size) {
    const int*   x    = (const int*)d_in[0];
    const int*   v2c  = (const int*)d_in[2];
    const int*   v2r  = (const int*)d_in[3];
    const float* fw   = (const float*)d_in[4];
    const float* tw   = (const float*)d_in[5];
    const float* Rw   = (const float*)d_in[6];
    const float* W    = (const float*)d_in[7];
    const float* bias = (const float*)d_in[8];
    float4* out = (float4*)d_out;

    int ntok = in_sizes[0];
    int V    = in_sizes[2];

    static bool init_done = false;
    if (!init_done) {
        cudaFuncSetAttribute(k_gemm, cudaFuncAttributeMaxDynamicSharedMemorySize,
                             SMEMF * (int)sizeof(float));
        init_done = true;
    }

    k_wprep<<<(E_ * PPAD + 255) / 256, 256>>>(W);
    k_ptab<<<(V + 255) / 256, 256>>>(v2c, v2r, Rw, V);
    k_mobius<<<NMB, 256>>>(fw, tw);
    k_gemm<<<NBT, 256, SMEMF * sizeof(float)>>>(bias);

    int gthreads = ntok * 32;
    k_gather<<<(gthreads + 255) / 256, 256>>>(x, bias, out, ntok);
}